// round 5
// baseline (speedup 1.0000x reference)
#include <cuda_runtime.h>
#include <cstdint>
#include <math.h>

#define BATCH 4
#define LEN 2048
#define DMODEL 1024
#define NH 8
#define DHEAD 128
#define MROWS (BATCH * LEN)

__device__ float g_Q[NH * BATCH * LEN * DHEAD];    // [h][b][l][d]
__device__ float g_K[NH * BATCH * LEN * DHEAD];
__device__ float g_V[NH * BATCH * LEN * DHEAD];
__device__ float g_ctx[BATCH * LEN * DMODEL];      // [b][l][h*128+d]

// ---------------------------------------------------------------------------
// tf32 helpers (compute_103-legal)
// ---------------------------------------------------------------------------
__device__ __forceinline__ uint32_t f2tf32(float x) {
    uint32_t r;
    asm("cvt.rna.tf32.f32 %0, %1;" : "=r"(r) : "f"(x));
    return r;
}

__device__ __forceinline__ void mma_tf32(float& d0, float& d1, float& d2,
                                         float& d3, uint32_t a0, uint32_t a1,
                                         uint32_t a2, uint32_t a3, uint32_t b0,
                                         uint32_t b1) {
    asm volatile(
        "mma.sync.aligned.m16n8k8.row.col.f32.tf32.tf32.f32 "
        "{%0,%1,%2,%3}, {%4,%5,%6,%7}, {%8,%9}, {%0,%1,%2,%3};"
        : "+f"(d0), "+f"(d1), "+f"(d2), "+f"(d3)
        : "r"(a0), "r"(a1), "r"(a2), "r"(a3), "r"(b0), "r"(b1));
}

// ===========================================================================
// tf32 mma.sync NT-GEMM, software-pipelined:
// double-buffered smem + register prefetch, ONE __syncthreads per BK=16 step.
// ===========================================================================
#define SP 20
#define NKIT (DMODEL / 16)   // 64

template <int SCATTER>
__global__ void __launch_bounds__(256)
gemm_mma(const float* __restrict__ A, const float* __restrict__ W,
         float* __restrict__ C)
{
    __shared__ uint32_t As[2][128 * SP];
    __shared__ uint32_t Ws[2][128 * SP];

    const int tid = threadIdx.x;
    const int wid = tid >> 5;
    const int lane = tid & 31;
    const int wm = (wid >> 2) * 64;
    const int wn = (wid & 3) * 32;
    const int r = lane >> 2;
    const int c = lane & 3;
    const int m0 = blockIdx.x * 128;
    const int n0 = blockIdx.y * 128;

    const int grow0 = tid >> 2;
    const int grow1 = grow0 + 64;
    const int gcol = (tid & 3) * 4;

    const float* Ag0 = A + (size_t)(m0 + grow0) * DMODEL + gcol;
    const float* Ag1 = A + (size_t)(m0 + grow1) * DMODEL + gcol;
    const float* Wg0 = W + (size_t)(n0 + grow0) * DMODEL + gcol;
    const float* Wg1 = W + (size_t)(n0 + grow1) * DMODEL + gcol;

    float acc[4][4][4];
#pragma unroll
    for (int i = 0; i < 4; i++)
#pragma unroll
        for (int j = 0; j < 4; j++)
#pragma unroll
            for (int q = 0; q < 4; q++) acc[i][j][q] = 0.0f;

    // prologue: load tile 0, fill buffer 0
    float4 pa0 = *(const float4*)(Ag0);
    float4 pa1 = *(const float4*)(Ag1);
    float4 pw0 = *(const float4*)(Wg0);
    float4 pw1 = *(const float4*)(Wg1);
    {
        uint32_t* qa0 = As[0] + grow0 * SP + gcol;
        uint32_t* qa1 = As[0] + grow1 * SP + gcol;
        uint32_t* qw0 = Ws[0] + grow0 * SP + gcol;
        uint32_t* qw1 = Ws[0] + grow1 * SP + gcol;
        qa0[0] = f2tf32(pa0.x); qa0[1] = f2tf32(pa0.y);
        qa0[2] = f2tf32(pa0.z); qa0[3] = f2tf32(pa0.w);
        qa1[0] = f2tf32(pa1.x); qa1[1] = f2tf32(pa1.y);
        qa1[2] = f2tf32(pa1.z); qa1[3] = f2tf32(pa1.w);
        qw0[0] = f2tf32(pw0.x); qw0[1] = f2tf32(pw0.y);
        qw0[2] = f2tf32(pw0.z); qw0[3] = f2tf32(pw0.w);
        qw1[0] = f2tf32(pw1.x); qw1[1] = f2tf32(pw1.y);
        qw1[2] = f2tf32(pw1.z); qw1[3] = f2tf32(pw1.w);
    }
    __syncthreads();

    for (int it = 0; it < NKIT; it++) {
        const int buf = it & 1;
        const bool more = (it + 1) < NKIT;
        // prefetch next tile into registers (global ld issued under MMAs)
        if (more) {
            const int k0 = (it + 1) * 16;
            pa0 = *(const float4*)(Ag0 + k0);
            pa1 = *(const float4*)(Ag1 + k0);
            pw0 = *(const float4*)(Wg0 + k0);
            pw1 = *(const float4*)(Wg1 + k0);
        }

        // compute from current buffer
#pragma unroll
        for (int ks = 0; ks < 2; ks++) {
            const int kc = ks * 8 + c;
            uint32_t af[4][4];
#pragma unroll
            for (int mt = 0; mt < 4; mt++) {
                const int m = wm + mt * 16;
                af[mt][0] = As[buf][(m + r) * SP + kc];
                af[mt][1] = As[buf][(m + r + 8) * SP + kc];
                af[mt][2] = As[buf][(m + r) * SP + kc + 4];
                af[mt][3] = As[buf][(m + r + 8) * SP + kc + 4];
            }
            uint32_t bf[4][2];
#pragma unroll
            for (int nt = 0; nt < 4; nt++) {
                const int n = wn + nt * 8 + r;
                bf[nt][0] = Ws[buf][n * SP + kc];
                bf[nt][1] = Ws[buf][n * SP + kc + 4];
            }
#pragma unroll
            for (int mt = 0; mt < 4; mt++)
#pragma unroll
                for (int nt = 0; nt < 4; nt++)
                    mma_tf32(acc[mt][nt][0], acc[mt][nt][1], acc[mt][nt][2],
                             acc[mt][nt][3], af[mt][0], af[mt][1], af[mt][2],
                             af[mt][3], bf[nt][0], bf[nt][1]);
        }

        // store prefetched tile into the other buffer; single barrier
        if (more) {
            const int nb = buf ^ 1;
            uint32_t* qa0 = As[nb] + grow0 * SP + gcol;
            uint32_t* qa1 = As[nb] + grow1 * SP + gcol;
            uint32_t* qw0 = Ws[nb] + grow0 * SP + gcol;
            uint32_t* qw1 = Ws[nb] + grow1 * SP + gcol;
            qa0[0] = f2tf32(pa0.x); qa0[1] = f2tf32(pa0.y);
            qa0[2] = f2tf32(pa0.z); qa0[3] = f2tf32(pa0.w);
            qa1[0] = f2tf32(pa1.x); qa1[1] = f2tf32(pa1.y);
            qa1[2] = f2tf32(pa1.z); qa1[3] = f2tf32(pa1.w);
            qw0[0] = f2tf32(pw0.x); qw0[1] = f2tf32(pw0.y);
            qw0[2] = f2tf32(pw0.z); qw0[3] = f2tf32(pw0.w);
            qw1[0] = f2tf32(pw1.x); qw1[1] = f2tf32(pw1.y);
            qw1[2] = f2tf32(pw1.z); qw1[3] = f2tf32(pw1.w);
            __syncthreads();
        }
    }

    // epilogue (unchanged)
#pragma unroll
    for (int mt = 0; mt < 4; mt++) {
#pragma unroll
        for (int half = 0; half < 2; half++) {
            const int mrow = m0 + wm + mt * 16 + r + half * 8;
            float* dst;
            if (SCATTER) {
                const int bb = mrow >> 11;
                const int ll = mrow & (LEN - 1);
                const int hh = n0 >> 7;
                dst = C + (((size_t)(hh * BATCH + bb) * LEN + ll) << 7);
            } else {
                dst = C + (size_t)mrow * DMODEL + n0;
            }
#pragma unroll
            for (int nt = 0; nt < 4; nt++) {
                const int ncol = wn + nt * 8 + 2 * c;
                *(float2*)(dst + ncol) =
                    make_float2(acc[mt][nt][half * 2], acc[mt][nt][half * 2 + 1]);
            }
        }
    }
}

// ===========================================================================
// Flash attention via mma.sync tf32 (unchanged from R4).
// ===========================================================================
#define ASP 132
#define BSP 68
#define SMA_Q 0
#define SMA_K (128 * ASP)
#define SMA_V (SMA_K + 64 * ASP)
#define SMA_P (SMA_V + 128 * BSP)
#define SMA_TOT (SMA_P + 128 * BSP)
#define SMEM_ATTN (SMA_TOT * (int)sizeof(uint32_t))

__global__ void __launch_bounds__(256)
attn_mma(const int* __restrict__ seq)
{
    extern __shared__ uint32_t sm[];
    uint32_t* Qs = sm + SMA_Q;
    uint32_t* Ks = sm + SMA_K;
    uint32_t* Vt = sm + SMA_V;
    uint32_t* Ps = sm + SMA_P;

    const int tid = threadIdx.x;
    const int wid = tid >> 5;
    const int lane = tid & 31;
    const int r = lane >> 2;
    const int c = lane & 3;
    const int qt = blockIdx.x, b = blockIdx.y, h = blockIdx.z;
    const int qbase = qt * 128;
    const int slen = seq[b];
    const int q0 = wid * 16;

    float* ctx = g_ctx + (size_t)b * LEN * DMODEL + (size_t)h * DHEAD;

    if (qbase >= slen) {
#pragma unroll
        for (int it = 0; it < 16; it++) {
            const int f = tid + it * 256;
            const int row = f >> 5;
            const int col = (f & 31) * 4;
            *(float4*)(ctx + (size_t)(qbase + row) * DMODEL + col) =
                make_float4(0.f, 0.f, 0.f, 0.f);
        }
        return;
    }

    const float* Qg = g_Q + (((size_t)h * BATCH + b) * LEN + qbase) * DHEAD;
    const float* Kg = g_K + ((size_t)h * BATCH + b) * LEN * DHEAD;
    const float* Vg = g_V + ((size_t)h * BATCH + b) * LEN * DHEAD;

    {
        const float scl = 0.08838834764831845f;
#pragma unroll
        for (int it = 0; it < 16; it++) {
            const int f = tid + it * 256;
            const int row = f >> 5;
            const int col = (f & 31) * 4;
            const float4 v = *(const float4*)(Qg + (size_t)row * DHEAD + col);
            uint32_t* p = Qs + row * ASP + col;
            p[0] = f2tf32(v.x * scl); p[1] = f2tf32(v.y * scl);
            p[2] = f2tf32(v.z * scl); p[3] = f2tf32(v.w * scl);
        }
    }
    __syncthreads();

    uint32_t qf[16][4];
#pragma unroll
    for (int ks = 0; ks < 16; ks++) {
        const int kc = ks * 8 + c;
        qf[ks][0] = Qs[(q0 + r) * ASP + kc];
        qf[ks][1] = Qs[(q0 + r + 8) * ASP + kc];
        qf[ks][2] = Qs[(q0 + r) * ASP + kc + 4];
        qf[ks][3] = Qs[(q0 + r + 8) * ASP + kc + 4];
    }

    float o[16][4];
#pragma unroll
    for (int nt = 0; nt < 16; nt++)
#pragma unroll
        for (int q = 0; q < 4; q++) o[nt][q] = 0.0f;
    float m0v = -1e30f, m1v = -1e30f, l0 = 0.0f, l1 = 0.0f;

    const int nkt = (slen + 63) >> 6;
    for (int kt = 0; kt < nkt; kt++) {
        const int kb = kt * 64;
        __syncthreads();

#pragma unroll
        for (int it = 0; it < 8; it++) {
            const int f = tid + it * 256;
            const int row = f >> 5;
            const int col = (f & 31) * 4;
            const float4 v =
                *(const float4*)(Kg + (size_t)(kb + row) * DHEAD + col);
            uint32_t* p = Ks + row * ASP + col;
            p[0] = f2tf32(v.x); p[1] = f2tf32(v.y);
            p[2] = f2tf32(v.z); p[3] = f2tf32(v.w);
        }
#pragma unroll
        for (int it = 0; it < 8; it++) {
            const int f = tid + it * 256;
            const int j = f >> 5;
            const int d = (f & 31) * 4;
            const float4 v =
                *(const float4*)(Vg + (size_t)(kb + j) * DHEAD + d);
            Vt[(d + 0) * BSP + j] = f2tf32(v.x);
            Vt[(d + 1) * BSP + j] = f2tf32(v.y);
            Vt[(d + 2) * BSP + j] = f2tf32(v.z);
            Vt[(d + 3) * BSP + j] = f2tf32(v.w);
        }
        __syncthreads();

        float s[8][4];
#pragma unroll
        for (int nt = 0; nt < 8; nt++)
#pragma unroll
            for (int q = 0; q < 4; q++) s[nt][q] = 0.0f;

#pragma unroll
        for (int ks = 0; ks < 16; ks++) {
            const int kc = ks * 8 + c;
            uint32_t bf[8][2];
#pragma unroll
            for (int nt = 0; nt < 8; nt++) {
                bf[nt][0] = Ks[(nt * 8 + r) * ASP + kc];
                bf[nt][1] = Ks[(nt * 8 + r) * ASP + kc + 4];
            }
#pragma unroll
            for (int nt = 0; nt < 8; nt++)
                mma_tf32(s[nt][0], s[nt][1], s[nt][2], s[nt][3],
                         qf[ks][0], qf[ks][1], qf[ks][2], qf[ks][3],
                         bf[nt][0], bf[nt][1]);
        }

#pragma unroll
        for (int nt = 0; nt < 8; nt++) {
            const int j0 = kb + nt * 8 + 2 * c;
            if (j0 >= slen)     { s[nt][0] = -1e30f; s[nt][2] = -1e30f; }
            if (j0 + 1 >= slen) { s[nt][1] = -1e30f; s[nt][3] = -1e30f; }
        }

        float mt0 = -1e30f, mt1 = -1e30f;
#pragma unroll
        for (int nt = 0; nt < 8; nt++) {
            mt0 = fmaxf(mt0, fmaxf(s[nt][0], s[nt][1]));
            mt1 = fmaxf(mt1, fmaxf(s[nt][2], s[nt][3]));
        }
        mt0 = fmaxf(mt0, __shfl_xor_sync(0xffffffffu, mt0, 1));
        mt0 = fmaxf(mt0, __shfl_xor_sync(0xffffffffu, mt0, 2));
        mt1 = fmaxf(mt1, __shfl_xor_sync(0xffffffffu, mt1, 1));
        mt1 = fmaxf(mt1, __shfl_xor_sync(0xffffffffu, mt1, 2));

        const float mn0 = fmaxf(m0v, mt0);
        const float mn1 = fmaxf(m1v, mt1);
        const float sc0 = __expf(m0v - mn0);
        const float sc1 = __expf(m1v - mn1);
        m0v = mn0; m1v = mn1;

        float rs0 = 0.0f, rs1 = 0.0f;
#pragma unroll
        for (int nt = 0; nt < 8; nt++) {
            const float p0 = __expf(s[nt][0] - mn0);
            const float p1 = __expf(s[nt][1] - mn0);
            const float p2 = __expf(s[nt][2] - mn1);
            const float p3 = __expf(s[nt][3] - mn1);
            rs0 += p0 + p1;
            rs1 += p2 + p3;
            uint32_t* pa = Ps + (q0 + r) * BSP + nt * 8 + 2 * c;
            pa[0] = f2tf32(p0); pa[1] = f2tf32(p1);
            uint32_t* pb = Ps + (q0 + r + 8) * BSP + nt * 8 + 2 * c;
            pb[0] = f2tf32(p2); pb[1] = f2tf32(p3);
        }
        rs0 += __shfl_xor_sync(0xffffffffu, rs0, 1);
        rs0 += __shfl_xor_sync(0xffffffffu, rs0, 2);
        rs1 += __shfl_xor_sync(0xffffffffu, rs1, 1);
        rs1 += __shfl_xor_sync(0xffffffffu, rs1, 2);
        l0 = l0 * sc0 + rs0;
        l1 = l1 * sc1 + rs1;

#pragma unroll
        for (int nt = 0; nt < 16; nt++) {
            o[nt][0] *= sc0; o[nt][1] *= sc0;
            o[nt][2] *= sc1; o[nt][3] *= sc1;
        }
        __syncwarp();

#pragma unroll
        for (int ks = 0; ks < 8; ks++) {
            const int kc = ks * 8 + c;
            uint32_t af[4];
            af[0] = Ps[(q0 + r) * BSP + kc];
            af[1] = Ps[(q0 + r + 8) * BSP + kc];
            af[2] = Ps[(q0 + r) * BSP + kc + 4];
            af[3] = Ps[(q0 + r + 8) * BSP + kc + 4];
#pragma unroll
            for (int nt = 0; nt < 16; nt++) {
                const uint32_t b0 = Vt[(nt * 8 + r) * BSP + kc];
                const uint32_t b1 = Vt[(nt * 8 + r) * BSP + kc + 4];
                mma_tf32(o[nt][0], o[nt][1], o[nt][2], o[nt][3],
                         af[0], af[1], af[2], af[3], b0, b1);
            }
        }
    }

    const int qr0 = qbase + q0 + r;
    const int qr1 = qr0 + 8;
    const float inv0 = (qr0 < slen) ? (1.0f / l0) : 0.0f;
    const float inv1 = (qr1 < slen) ? (1.0f / l1) : 0.0f;
#pragma unroll
    for (int nt = 0; nt < 16; nt++) {
        const int col = nt * 8 + 2 * c;
        *(float2*)(ctx + (size_t)qr0 * DMODEL + col) =
            make_float2(o[nt][0] * inv0, o[nt][1] * inv0);
        *(float2*)(ctx + (size_t)qr1 * DMODEL + col) =
            make_float2(o[nt][2] * inv1, o[nt][3] * inv1);
    }
}

// ===========================================================================
extern "C" void kernel_launch(void* const* d_in, const int* in_sizes, int n_in,
                              void* d_out, int out_size)
{
    (void)in_sizes; (void)n_in; (void)out_size;
    const float* queries = (const float*)d_in[0];
    const float* keys    = (const float*)d_in[1];
    const int*   seqlen  = (const int*)d_in[2];
    const float* Wq      = (const float*)d_in[3];
    const float* Wk      = (const float*)d_in[4];
    const float* Wv      = (const float*)d_in[5];
    const float* Wo      = (const float*)d_in[6];
    float* out = (float*)d_out;

    void *pQ, *pK, *pV, *pC;
    cudaGetSymbolAddress(&pQ, g_Q);
    cudaGetSymbolAddress(&pK, g_K);
    cudaGetSymbolAddress(&pV, g_V);
    cudaGetSymbolAddress(&pC, g_ctx);

    cudaFuncSetAttribute(attn_mma,
                         cudaFuncAttributeMaxDynamicSharedMemorySize,
                         SMEM_ATTN);

    const dim3 gg(MROWS / 128, DMODEL / 128);
    gemm_mma<1><<<gg, 256>>>(queries, Wq, (float*)pQ);
    gemm_mma<1><<<gg, 256>>>(keys,    Wk, (float*)pK);
    gemm_mma<1><<<gg, 256>>>(keys,    Wv, (float*)pV);

    attn_mma<<<dim3(LEN / 128, BATCH, NH), 256, SMEM_ATTN>>>(seqlen);

    gemm_mma<0><<<gg, 256>>>((const float*)pC, Wo, out);
}